// round 7
// baseline (speedup 1.0000x reference)
#include <cuda_runtime.h>
#include <cuda_bf16.h>
#include <stdint.h>

#define N_MAX 50000
#define E_MAX 800000
#define DH 64

// ---------------- device scratch ---------------------------------------------
__device__ __align__(256) float g_bufA[N_MAX * DH];   // xw (GEMM out)
__device__ __align__(256) float g_bufB[N_MAX * DH];   // agg (gather out / next in)
__device__ __align__(16)  float g_dis[N_MAX];
__device__ __align__(16)  int   g_cnt[N_MAX];
__device__ __align__(16)  int   g_fill[N_MAX];
__device__ __align__(16)  int   g_rowptr[N_MAX + 1];
__device__ __align__(16)  int2  g_csr[E_MAX];          // (src, norm-as-int)
__device__ int g_is64;

// ---------------- edge dtype detect ------------------------------------------
__global__ void k_detect(const int* __restrict__ w) {
    int allz = 1;
#pragma unroll
    for (int i = 1; i < 64; i += 2) allz &= (w[i] == 0);
    g_is64 = allz;
}

// ---------------- pass 1: degree histogram (reads edge_index directly) --------
__global__ void k_hist(const void* __restrict__ ei, int E) {
    int e = blockIdx.x * blockDim.x + threadIdx.x;
    if (e >= E) return;
    int d;
    if (g_is64) d = (int)((const long long*)ei)[e + E];
    else        d = ((const int*)ei)[e + E];
    atomicAdd(&g_cnt[d], 1);
}

// ---------------- single-block scan: rowptr, dis, fill=0 -----------------------
__global__ __launch_bounds__(1024) void k_scan_dis(int n, int E) {
    const int T = 1024;
    int t = threadIdx.x;
    int C = (n + T - 1) / T;
    int lo = t * C;
    int hi = lo + C < n ? lo + C : n;

    int sum = 0;
    for (int i = lo; i < hi; i++) sum += g_cnt[i];

    __shared__ int wsum[32];
    int lane = t & 31, wid = t >> 5;
    int v = sum;
#pragma unroll
    for (int o = 1; o < 32; o <<= 1) {
        int u = __shfl_up_sync(0xffffffffu, v, o);
        if (lane >= o) v += u;
    }
    if (lane == 31) wsum[wid] = v;
    __syncthreads();
    if (wid == 0) {
        int w = wsum[lane];
#pragma unroll
        for (int o = 1; o < 32; o <<= 1) {
            int u = __shfl_up_sync(0xffffffffu, w, o);
            if (lane >= o) w += u;
        }
        wsum[lane] = w;
    }
    __syncthreads();
    int run = (v - sum) + (wid > 0 ? wsum[wid - 1] : 0);   // exclusive prefix

    for (int i = lo; i < hi; i++) {
        int cv = g_cnt[i];
        g_rowptr[i] = run;
        run += cv;
        g_dis[i] = rsqrtf((float)(cv + 1));
        g_fill[i] = 0;
    }
    if (t == T - 1) g_rowptr[n] = E;
}

// ---------------- pass 2: CSR fill (reads edge_index directly) -----------------
__global__ void k_fill(const void* __restrict__ ei, int E) {
    int e = blockIdx.x * blockDim.x + threadIdx.x;
    if (e >= E) return;
    int s, d;
    if (g_is64) {
        const long long* p = (const long long*)ei;
        s = (int)p[e];
        d = (int)p[e + E];
    } else {
        const int* p = (const int*)ei;
        s = p[e];
        d = p[e + E];
    }
    int pos = g_rowptr[d] + atomicAdd(&g_fill[d], 1);
    float nrm = g_dis[s] * g_dis[d];
    g_csr[pos] = make_int2(s, __float_as_int(nrm));
}

// ---------------- GEMM: out[n,64] = f(in[n,:]) @ W (64x64) ---------------------
// f = relu(v + bias_in) when RELU. 4 threads/node, 16 cols each.
template <bool RELU>
__global__ __launch_bounds__(256) void k_gemm64(
    const float* __restrict__ in, float* __restrict__ outp,
    const float* __restrict__ W, const float* __restrict__ bias_in, int n)
{
    __shared__ float Ws[64 * 64];
    __shared__ float bs[64];
    int tid = threadIdx.x;
#pragma unroll
    for (int i = tid; i < 64 * 64 / 4; i += 256)
        ((float4*)Ws)[i] = ((const float4*)W)[i];
    if (RELU && tid < 16) ((float4*)bs)[tid] = ((const float4*)bias_in)[tid];
    __syncthreads();

    int node = blockIdx.x * 64 + (tid >> 2);
    int quad = tid & 3;
    if (node >= n) return;

    float acc[16];
#pragma unroll
    for (int j = 0; j < 16; j++) acc[j] = 0.f;

    const float4* xr4 = (const float4*)(in + (size_t)node * 64);
    for (int k4 = 0; k4 < 16; k4++) {
        float4 v4 = xr4[k4];
        float vv[4] = {v4.x, v4.y, v4.z, v4.w};
#pragma unroll
        for (int u = 0; u < 4; u++) {
            int k = k4 * 4 + u;
            float v = vv[u];
            if (RELU) v = fmaxf(v + bs[k], 0.f);
            const float* wrow = &Ws[k * 64 + quad * 16];
#pragma unroll
            for (int j = 0; j < 16; j++) acc[j] = fmaf(v, wrow[j], acc[j]);
        }
    }
    float* op = outp + (size_t)node * 64 + quad * 16;
#pragma unroll
    for (int j = 0; j < 16; j += 4)
        *(float4*)(op + j) = make_float4(acc[j], acc[j + 1], acc[j + 2], acc[j + 3]);
}

// ---------------- CSR gather: agg[v] = dis[v]^2*xw[v] + sum xw[s]*norm ---------
// 16 threads/node, one float4 column each. 4-wide neighbor unroll for MLP.
__global__ __launch_bounds__(256) void k_gather(
    const float* __restrict__ fin, float* __restrict__ fout, int n)
{
    int tid = threadIdx.x;
    int node = blockIdx.x * 16 + (tid >> 4);
    int c = tid & 15;
    if (node >= n) return;

    float dv = g_dis[node];
    float sl = dv * dv;
    const float4* xa = (const float4*)fin;
    float4 me = xa[node * 16 + c];
    float ax = me.x * sl, ay = me.y * sl, az = me.z * sl, aw = me.w * sl;

    int p   = g_rowptr[node];
    int end = g_rowptr[node + 1];

    for (; p + 3 < end; p += 4) {
        int2 e0 = g_csr[p];
        int2 e1 = g_csr[p + 1];
        int2 e2 = g_csr[p + 2];
        int2 e3 = g_csr[p + 3];
        float4 v0 = xa[e0.x * 16 + c];
        float4 v1 = xa[e1.x * 16 + c];
        float4 v2 = xa[e2.x * 16 + c];
        float4 v3 = xa[e3.x * 16 + c];
        float n0 = __int_as_float(e0.y);
        float n1 = __int_as_float(e1.y);
        float n2 = __int_as_float(e2.y);
        float n3 = __int_as_float(e3.y);
        ax = fmaf(v0.x, n0, ax); ay = fmaf(v0.y, n0, ay);
        az = fmaf(v0.z, n0, az); aw = fmaf(v0.w, n0, aw);
        ax = fmaf(v1.x, n1, ax); ay = fmaf(v1.y, n1, ay);
        az = fmaf(v1.z, n1, az); aw = fmaf(v1.w, n1, aw);
        ax = fmaf(v2.x, n2, ax); ay = fmaf(v2.y, n2, ay);
        az = fmaf(v2.z, n2, az); aw = fmaf(v2.w, n2, aw);
        ax = fmaf(v3.x, n3, ax); ay = fmaf(v3.y, n3, ay);
        az = fmaf(v3.z, n3, az); aw = fmaf(v3.w, n3, aw);
    }
    for (; p < end; p++) {
        int2 e0 = g_csr[p];
        float n0 = __int_as_float(e0.y);
        float4 v0 = xa[e0.x * 16 + c];
        ax = fmaf(v0.x, n0, ax); ay = fmaf(v0.y, n0, ay);
        az = fmaf(v0.z, n0, az); aw = fmaf(v0.w, n0, aw);
    }
    ((float4*)fout)[node * 16 + c] = make_float4(ax, ay, az, aw);
}

// ---------------- final linear: out = relu(agg2 + b2) @ linW + linb ------------
__global__ __launch_bounds__(256) void k_final(
    const float* __restrict__ fin,
    const float* __restrict__ linW, const float* __restrict__ b2,
    const float* __restrict__ linb, float* __restrict__ out, int n)
{
    __shared__ float Ws[64 * 8];
    __shared__ float bs[64];
    __shared__ float lb[8];
    int tid = threadIdx.x;
#pragma unroll
    for (int i = tid; i < 128; i += 256) ((float4*)Ws)[i] = ((const float4*)linW)[i];
    if (tid < 16) ((float4*)bs)[tid] = ((const float4*)b2)[tid];
    if (tid < 2)  ((float4*)lb)[tid] = ((const float4*)linb)[tid];
    __syncthreads();

    int node = blockIdx.x * blockDim.x + tid;
    if (node >= n) return;

    float acc[8];
#pragma unroll
    for (int j = 0; j < 8; j++) acc[j] = lb[j];

    const float* xr = fin + (size_t)node * 64;
    for (int k = 0; k < 64; k++) {
        float v = fmaxf(xr[k] + bs[k], 0.f);
        const float* wrow = &Ws[k * 8];
#pragma unroll
        for (int j = 0; j < 8; j++) acc[j] = fmaf(v, wrow[j], acc[j]);
    }
    float* op = out + (size_t)node * 8;
#pragma unroll
    for (int j = 0; j < 8; j += 4)
        *(float4*)(op + j) = make_float4(acc[j], acc[j + 1], acc[j + 2], acc[j + 3]);
}

// ---------------- host launcher ------------------------------------------------
extern "C" void kernel_launch(void* const* d_in, const int* in_sizes, int n_in,
                              void* d_out, int out_size)
{
    const float* x    = (const float*)d_in[0];
    const void*  ei   = d_in[1];
    const float* W0   = (const float*)d_in[2];
    const float* b0   = (const float*)d_in[3];
    const float* W1   = (const float*)d_in[4];
    const float* b1   = (const float*)d_in[5];
    const float* W2   = (const float*)d_in[6];
    const float* b2   = (const float*)d_in[7];
    const float* linW = (const float*)d_in[8];
    const float* linb = (const float*)d_in[9];
    float* out = (float*)d_out;

    int N = in_sizes[0] / DH;       // 50000
    int E = in_sizes[1] / 2;        // 800000

    const int T = 256;
    int gN = (N + T - 1) / T;       // 196
    int gE = (E + T - 1) / T;       // 3125
    int gG = (N + 63) / 64;         // 782
    int gA = (N + 15) / 16;         // 3125

    // One-time host-side setup (first call is the uncaptured correctness run).
    static float* bufA = nullptr;
    static float* bufB = nullptr;
    static int*   cntP = nullptr;
    static cudaStream_t s2;
    static cudaEvent_t evFork, evJoin;
    if (!bufA) {
        void* p;
        cudaGetSymbolAddress(&p, g_bufA); bufA = (float*)p;
        cudaGetSymbolAddress(&p, g_bufB); bufB = (float*)p;
        cudaGetSymbolAddress(&p, g_cnt);  cntP = (int*)p;
        cudaStreamCreateWithFlags(&s2, cudaStreamNonBlocking);
        cudaEventCreateWithFlags(&evFork, cudaEventDisableTiming);
        cudaEventCreateWithFlags(&evJoin, cudaEventDisableTiming);
    }

    // Fork: layer-0 GEMM (depends only on x, W0) overlaps the CSR build.
    cudaEventRecord(evFork, 0);
    cudaStreamWaitEvent(s2, evFork, 0);
    k_gemm64<false><<<gG, T, 0, s2>>>(x, bufA, W0, nullptr, N);
    cudaEventRecord(evJoin, s2);

    // CSR build on the main stream.
    cudaMemsetAsync(cntP, 0, (size_t)N * sizeof(int));
    k_detect<<<1, 1>>>((const int*)ei);
    k_hist<<<gE, T>>>(ei, E);
    k_scan_dis<<<1, 1024>>>(N, E);
    k_fill<<<gE, T>>>(ei, E);

    // Join before the first gather consumes bufA.
    cudaStreamWaitEvent(0, evJoin, 0);

    // layer 0 aggregate
    k_gather<<<gA, T>>>(bufA, bufB, N);
    // layer 1
    k_gemm64<true><<<gG, T>>>(bufB, bufA, W1, b0, N);
    k_gather<<<gA, T>>>(bufA, bufB, N);
    // layer 2
    k_gemm64<true><<<gG, T>>>(bufB, bufA, W2, b1, N);
    k_gather<<<gA, T>>>(bufA, bufB, N);
    // head
    k_final<<<gN, T>>>(bufB, linW, b2, linb, out, N);
}

// round 8
// speedup vs baseline: 1.3736x; 1.3736x over previous
#include <cuda_runtime.h>
#include <cuda_bf16.h>
#include <stdint.h>

#define N_MAX 50000
#define E_MAX 800000
#define DH 64
#define SCAN_B 256
#define NBLK ((N_MAX + SCAN_B - 1) / SCAN_B)   // 196

// ---------------- device scratch ---------------------------------------------
__device__ __align__(256) float g_bufA[N_MAX * DH];   // xw (GEMM out)
__device__ __align__(256) float g_bufB[N_MAX * DH];   // agg (gather out / next in)
__device__ __align__(16)  float g_dis[N_MAX];
__device__ __align__(16)  int   g_cnt[N_MAX];
__device__ __align__(16)  int   g_fill[N_MAX];
__device__ __align__(16)  int   g_rowptr[N_MAX + 1];
__device__ __align__(16)  int   g_bsum[NBLK];
__device__ __align__(16)  int   g_boff[NBLK];
__device__ __align__(16)  int2  g_csr[E_MAX];          // (src, norm-as-int)
__device__ int g_is64;

// ---------------- edge dtype detect ------------------------------------------
__global__ void k_detect(const int* __restrict__ w) {
    int allz = 1;
#pragma unroll
    for (int i = 1; i < 64; i += 2) allz &= (w[i] == 0);
    g_is64 = allz;
}

// ---------------- pass 1: degree histogram ------------------------------------
__global__ void k_hist(const void* __restrict__ ei, int E) {
    int e = blockIdx.x * blockDim.x + threadIdx.x;
    if (e >= E) return;
    int d;
    if (g_is64) d = (int)((const long long*)ei)[e + E];
    else        d = ((const int*)ei)[e + E];
    atomicAdd(&g_cnt[d], 1);
}

// ---------------- multi-block exclusive scan of g_cnt -> g_rowptr --------------
__global__ __launch_bounds__(SCAN_B) void k_scan1(int n) {
    __shared__ int s[SCAN_B];
    int t = threadIdx.x;
    int i = blockIdx.x * SCAN_B + t;
    int v = (i < n) ? g_cnt[i] : 0;
    s[t] = v;
    __syncthreads();
#pragma unroll
    for (int off = 1; off < SCAN_B; off <<= 1) {
        int add = (t >= off) ? s[t - off] : 0;
        __syncthreads();
        s[t] += add;
        __syncthreads();
    }
    if (i < n) g_rowptr[i] = s[t] - v;           // exclusive within block
    if (t == SCAN_B - 1) g_bsum[blockIdx.x] = s[t];
}

__global__ __launch_bounds__(SCAN_B) void k_scan2(int nblk) {
    __shared__ int s[SCAN_B];
    int t = threadIdx.x;
    int v = (t < nblk) ? g_bsum[t] : 0;
    s[t] = v;
    __syncthreads();
#pragma unroll
    for (int off = 1; off < SCAN_B; off <<= 1) {
        int add = (t >= off) ? s[t - off] : 0;
        __syncthreads();
        s[t] += add;
        __syncthreads();
    }
    if (t < nblk) g_boff[t] = s[t] - v;          // exclusive
}

// scan3: add block offsets; also dis = rsqrt(deg+1), fill = 0, rowptr[n] = E.
__global__ __launch_bounds__(SCAN_B) void k_scan3(int n, int E) {
    int i = blockIdx.x * SCAN_B + threadIdx.x;
    if (i < n) {
        g_rowptr[i] += g_boff[blockIdx.x];
        g_dis[i] = rsqrtf((float)(g_cnt[i] + 1));
        g_fill[i] = 0;
    }
    if (i == 0) g_rowptr[n] = E;
}

// ---------------- pass 2: CSR fill ---------------------------------------------
__global__ void k_fill(const void* __restrict__ ei, int E) {
    int e = blockIdx.x * blockDim.x + threadIdx.x;
    if (e >= E) return;
    int s, d;
    if (g_is64) {
        const long long* p = (const long long*)ei;
        s = (int)p[e];
        d = (int)p[e + E];
    } else {
        const int* p = (const int*)ei;
        s = p[e];
        d = p[e + E];
    }
    int pos = g_rowptr[d] + atomicAdd(&g_fill[d], 1);
    float nrm = g_dis[s] * g_dis[d];
    g_csr[pos] = make_int2(s, __float_as_int(nrm));
}

// ---------------- GEMM: out[n,64] = f(in[n,:]) @ W (64x64) ---------------------
template <bool RELU>
__global__ __launch_bounds__(256) void k_gemm64(
    const float* __restrict__ in, float* __restrict__ outp,
    const float* __restrict__ W, const float* __restrict__ bias_in, int n)
{
    __shared__ float Ws[64 * 64];
    __shared__ float bs[64];
    int tid = threadIdx.x;
#pragma unroll
    for (int i = tid; i < 64 * 64 / 4; i += 256)
        ((float4*)Ws)[i] = ((const float4*)W)[i];
    if (RELU && tid < 16) ((float4*)bs)[tid] = ((const float4*)bias_in)[tid];
    __syncthreads();

    int node = blockIdx.x * 64 + (tid >> 2);
    int quad = tid & 3;
    if (node >= n) return;

    float acc[16];
#pragma unroll
    for (int j = 0; j < 16; j++) acc[j] = 0.f;

    const float4* xr4 = (const float4*)(in + (size_t)node * 64);
    for (int k4 = 0; k4 < 16; k4++) {
        float4 v4 = xr4[k4];
        float vv[4] = {v4.x, v4.y, v4.z, v4.w};
#pragma unroll
        for (int u = 0; u < 4; u++) {
            int k = k4 * 4 + u;
            float v = vv[u];
            if (RELU) v = fmaxf(v + bs[k], 0.f);
            const float* wrow = &Ws[k * 64 + quad * 16];
#pragma unroll
            for (int j = 0; j < 16; j++) acc[j] = fmaf(v, wrow[j], acc[j]);
        }
    }
    float* op = outp + (size_t)node * 64 + quad * 16;
#pragma unroll
    for (int j = 0; j < 16; j += 4)
        *(float4*)(op + j) = make_float4(acc[j], acc[j + 1], acc[j + 2], acc[j + 3]);
}

// ---------------- CSR gather: agg[v] = dis[v]^2*xw[v] + sum xw[s]*norm ---------
__global__ __launch_bounds__(256) void k_gather(
    const float* __restrict__ fin, float* __restrict__ fout, int n)
{
    int tid = threadIdx.x;
    int node = blockIdx.x * 16 + (tid >> 4);
    int c = tid & 15;
    if (node >= n) return;

    float dv = g_dis[node];
    float sl = dv * dv;
    const float4* xa = (const float4*)fin;
    float4 me = xa[node * 16 + c];
    float ax = me.x * sl, ay = me.y * sl, az = me.z * sl, aw = me.w * sl;

    int p   = g_rowptr[node];
    int end = g_rowptr[node + 1];

    for (; p + 3 < end; p += 4) {
        int2 e0 = g_csr[p];
        int2 e1 = g_csr[p + 1];
        int2 e2 = g_csr[p + 2];
        int2 e3 = g_csr[p + 3];
        float4 v0 = xa[e0.x * 16 + c];
        float4 v1 = xa[e1.x * 16 + c];
        float4 v2 = xa[e2.x * 16 + c];
        float4 v3 = xa[e3.x * 16 + c];
        float n0 = __int_as_float(e0.y);
        float n1 = __int_as_float(e1.y);
        float n2 = __int_as_float(e2.y);
        float n3 = __int_as_float(e3.y);
        ax = fmaf(v0.x, n0, ax); ay = fmaf(v0.y, n0, ay);
        az = fmaf(v0.z, n0, az); aw = fmaf(v0.w, n0, aw);
        ax = fmaf(v1.x, n1, ax); ay = fmaf(v1.y, n1, ay);
        az = fmaf(v1.z, n1, az); aw = fmaf(v1.w, n1, aw);
        ax = fmaf(v2.x, n2, ax); ay = fmaf(v2.y, n2, ay);
        az = fmaf(v2.z, n2, az); aw = fmaf(v2.w, n2, aw);
        ax = fmaf(v3.x, n3, ax); ay = fmaf(v3.y, n3, ay);
        az = fmaf(v3.z, n3, az); aw = fmaf(v3.w, n3, aw);
    }
    for (; p < end; p++) {
        int2 e0 = g_csr[p];
        float n0 = __int_as_float(e0.y);
        float4 v0 = xa[e0.x * 16 + c];
        ax = fmaf(v0.x, n0, ax); ay = fmaf(v0.y, n0, ay);
        az = fmaf(v0.z, n0, az); aw = fmaf(v0.w, n0, aw);
    }
    ((float4*)fout)[node * 16 + c] = make_float4(ax, ay, az, aw);
}

// ---------------- final linear: out = relu(agg2 + b2) @ linW + linb ------------
__global__ __launch_bounds__(256) void k_final(
    const float* __restrict__ fin,
    const float* __restrict__ linW, const float* __restrict__ b2,
    const float* __restrict__ linb, float* __restrict__ out, int n)
{
    __shared__ float Ws[64 * 8];
    __shared__ float bs[64];
    __shared__ float lb[8];
    int tid = threadIdx.x;
#pragma unroll
    for (int i = tid; i < 128; i += 256) ((float4*)Ws)[i] = ((const float4*)linW)[i];
    if (tid < 16) ((float4*)bs)[tid] = ((const float4*)b2)[tid];
    if (tid < 2)  ((float4*)lb)[tid] = ((const float4*)linb)[tid];
    __syncthreads();

    int node = blockIdx.x * blockDim.x + tid;
    if (node >= n) return;

    float acc[8];
#pragma unroll
    for (int j = 0; j < 8; j++) acc[j] = lb[j];

    const float* xr = fin + (size_t)node * 64;
    for (int k = 0; k < 64; k++) {
        float v = fmaxf(xr[k] + bs[k], 0.f);
        const float* wrow = &Ws[k * 8];
#pragma unroll
        for (int j = 0; j < 8; j++) acc[j] = fmaf(v, wrow[j], acc[j]);
    }
    float* op = out + (size_t)node * 8;
#pragma unroll
    for (int j = 0; j < 8; j += 4)
        *(float4*)(op + j) = make_float4(acc[j], acc[j + 1], acc[j + 2], acc[j + 3]);
}

// ---------------- host launcher ------------------------------------------------
extern "C" void kernel_launch(void* const* d_in, const int* in_sizes, int n_in,
                              void* d_out, int out_size)
{
    const float* x    = (const float*)d_in[0];
    const void*  ei   = d_in[1];
    const float* W0   = (const float*)d_in[2];
    const float* b0   = (const float*)d_in[3];
    const float* W1   = (const float*)d_in[4];
    const float* b1   = (const float*)d_in[5];
    const float* W2   = (const float*)d_in[6];
    const float* b2   = (const float*)d_in[7];
    const float* linW = (const float*)d_in[8];
    const float* linb = (const float*)d_in[9];
    float* out = (float*)d_out;

    int N = in_sizes[0] / DH;       // 50000
    int E = in_sizes[1] / 2;        // 800000

    const int T = 256;
    int gN = (N + T - 1) / T;       // 196
    int gE = (E + T - 1) / T;       // 3125
    int gG = (N + 63) / 64;         // 782
    int gA = (N + 15) / 16;         // 3125

    // One-time host-side setup (first call is the uncaptured correctness run).
    static float* bufA = nullptr;
    static float* bufB = nullptr;
    static int*   cntP = nullptr;
    static cudaStream_t s2;
    static cudaEvent_t evFork, evJoin;
    if (!bufA) {
        void* p;
        cudaGetSymbolAddress(&p, g_bufA); bufA = (float*)p;
        cudaGetSymbolAddress(&p, g_bufB); bufB = (float*)p;
        cudaGetSymbolAddress(&p, g_cnt);  cntP = (int*)p;
        cudaStreamCreateWithFlags(&s2, cudaStreamNonBlocking);
        cudaEventCreateWithFlags(&evFork, cudaEventDisableTiming);
        cudaEventCreateWithFlags(&evJoin, cudaEventDisableTiming);
    }

    // Fork: layer-0 GEMM (depends only on x, W0) overlaps the CSR build.
    cudaEventRecord(evFork, 0);
    cudaStreamWaitEvent(s2, evFork, 0);
    k_gemm64<false><<<gG, T, 0, s2>>>(x, bufA, W0, nullptr, N);
    cudaEventRecord(evJoin, s2);

    // CSR build on the main stream (multi-block scan — single-block scan was
    // a 102 us disaster per ncu round 7).
    cudaMemsetAsync(cntP, 0, (size_t)N * sizeof(int));
    k_detect<<<1, 1>>>((const int*)ei);
    k_hist<<<gE, T>>>(ei, E);
    k_scan1<<<gN, SCAN_B>>>(N);
    k_scan2<<<1, SCAN_B>>>(gN);
    k_scan3<<<gN, SCAN_B>>>(N, E);
    k_fill<<<gE, T>>>(ei, E);

    // Join before the first gather consumes bufA.
    cudaStreamWaitEvent(0, evJoin, 0);

    // layer 0 aggregate
    k_gather<<<gA, T>>>(bufA, bufB, N);
    // layer 1
    k_gemm64<true><<<gG, T>>>(bufB, bufA, W1, b0, N);
    k_gather<<<gA, T>>>(bufA, bufB, N);
    // layer 2
    k_gemm64<true><<<gG, T>>>(bufB, bufA, W2, b1, N);
    k_gather<<<gA, T>>>(bufA, bufB, N);
    // head
    k_final<<<gN, T>>>(bufB, linW, b2, linb, out, N);
}